// round 3
// baseline (speedup 1.0000x reference)
#include <cuda_runtime.h>
#include <cuda_bf16.h>
#include <stdint.h>

// Problem constants
#define NTOK   (32 * 8192)          // 262144 tokens
#define TILE_T 128                  // tokens per CTA (8 warps x 16)
#define NCTAS  (NTOK / TILE_T)      // 2048
#define RPQ    17                   // uint4 per smem W row (68 words, conflict-free)

// Split one float pair into bf16-hi and bf16-lo packed words (lo = residual).
__device__ __forceinline__ void split2(float x0, float x1, uint32_t& hi, uint32_t& lo) {
    __nv_bfloat16 h0 = __float2bfloat16(x0);
    __nv_bfloat16 h1 = __float2bfloat16(x1);
    __nv_bfloat16 l0 = __float2bfloat16(x0 - __bfloat162float(h0));
    __nv_bfloat16 l1 = __float2bfloat16(x1 - __bfloat162float(h1));
    hi = (uint32_t)__bfloat16_as_ushort(h0) | ((uint32_t)__bfloat16_as_ushort(h1) << 16);
    lo = (uint32_t)__bfloat16_as_ushort(l0) | ((uint32_t)__bfloat16_as_ushort(l1) << 16);
}

__device__ __forceinline__ void mma16816(float* c, const uint32_t* a, uint32_t b0, uint32_t b1) {
    asm volatile(
        "mma.sync.aligned.m16n8k16.row.col.f32.bf16.bf16.f32 "
        "{%0,%1,%2,%3}, {%4,%5,%6,%7}, {%8,%9}, {%0,%1,%2,%3};\n"
        : "+f"(c[0]), "+f"(c[1]), "+f"(c[2]), "+f"(c[3])
        : "r"(a[0]), "r"(a[1]), "r"(a[2]), "r"(a[3]), "r"(b0), "r"(b1));
}

__device__ __forceinline__ float2 ldcs2(const float* p) {
    float2 v;
    asm volatile("ld.global.cs.v2.f32 {%0,%1}, [%2];" : "=f"(v.x), "=f"(v.y) : "l"(p));
    return v;
}
__device__ __forceinline__ void stcs2(float* p, float a, float b) {
    asm volatile("st.global.cs.v2.f32 [%0], {%1,%2};" :: "l"(p), "f"(a), "f"(b));
}

__global__ void __launch_bounds__(256, 3)
quantum_fused_kernel(const float* __restrict__ x,
                     const float* __restrict__ Win,    // [64 wires][64 embed]
                     const float* __restrict__ theta,  // [64]
                     const float* __restrict__ Wout,   // [64 out][64 wires]
                     float* __restrict__ out)
{
    // Packed B-fragment quads: sW[row][kt*4+tc] = {hi(w), hi(w+4), lo(w), lo(w+4)},
    // w = kt*8+tc. Row pitch 17 uint4 (68 words) -> LDS.128 conflict-free.
    __shared__ uint4 sWin[64 * RPQ];
    __shared__ uint4 sWout[64 * RPQ];
    __shared__ float sTheta[64];

    const int tid = threadIdx.x;

    // One-time W split+pack: 64 rows x 16 packs = 1024 packs per array.
    for (int idx = tid; idx < 64 * 16; idx += 256) {
        const int row = idx >> 4;
        const int p   = idx & 15;          // kt*4 + tc
        const int kt  = p >> 2, tc = p & 3;
        const int w   = kt * 8 + tc;       // float2-word index in row

        float2 a = ((const float2*)Win)[row * 32 + w];
        float2 b = ((const float2*)Win)[row * 32 + w + 4];
        uint4 q;
        split2(a.x, a.y, q.x, q.z);
        split2(b.x, b.y, q.y, q.w);
        sWin[row * RPQ + p] = q;

        a = ((const float2*)Wout)[row * 32 + w];
        b = ((const float2*)Wout)[row * 32 + w + 4];
        split2(a.x, a.y, q.x, q.z);
        split2(b.x, b.y, q.y, q.w);
        sWout[row * RPQ + p] = q;
    }
    if (tid < 64) sTheta[tid] = theta[tid];
    __syncthreads();

    const int lane = tid & 31;
    const int warp = tid >> 5;    // 0..7
    const int gr   = lane >> 2;   // group-of-4 id (row within 8)
    const int tc   = lane & 3;    // thread-in-group (col pair selector)

    const int tok0 = blockIdx.x * TILE_T + warp * 16;   // 16 tokens per warp

    // ---------------- Front-batched x loads (MLP=16), streaming ----------------
    float2 v[16];
    const float* px = x + (size_t)(tok0 + gr) * 64 + tc * 2;
#pragma unroll
    for (int kt = 0; kt < 4; kt++) {
        v[kt * 4 + 0] = ldcs2(px + kt * 16);              // (gr,   kt*16+tc*2)
        v[kt * 4 + 1] = ldcs2(px + kt * 16 + 8 * 64);     // (gr+8, kt*16+tc*2)
        v[kt * 4 + 2] = ldcs2(px + kt * 16 + 8);          // (gr,   kt*16+tc*2+8)
        v[kt * 4 + 3] = ldcs2(px + kt * 16 + 8 * 64 + 8); // (gr+8, kt*16+tc*2+8)
    }

    uint32_t ah[4][4], al[4][4];
#pragma unroll
    for (int kt = 0; kt < 4; kt++)
#pragma unroll
        for (int i = 0; i < 4; i++)
            split2(v[kt * 4 + i].x, v[kt * 4 + i].y, ah[kt][i], al[kt][i]);

    // ---------------- GEMM1: T = X @ Win^T (bf16x3, fp32 acc) ----------------
    float acc[8][4];
#pragma unroll
    for (int nt = 0; nt < 8; nt++)
#pragma unroll
        for (int i = 0; i < 4; i++) acc[nt][i] = 0.f;

#pragma unroll
    for (int kt = 0; kt < 4; kt++) {
#pragma unroll
        for (int nt = 0; nt < 8; nt++) {
            const uint4 q = sWin[(nt * 8 + gr) * RPQ + kt * 4 + tc];
            mma16816(acc[nt], ah[kt], q.x, q.y);  // hi*hi
            mma16816(acc[nt], al[kt], q.x, q.y);  // lo*hi
            mma16816(acc[nt], ah[kt], q.z, q.w);  // hi*lo
        }
    }

    // -------- q = cos(T + theta); repack C-frags directly into A-frags --------
    uint32_t a2h[4][4], a2l[4][4];
#pragma unroll
    for (int kt2 = 0; kt2 < 4; kt2++) {
        const int ntA = 2 * kt2, ntB = 2 * kt2 + 1;
        const float tA0 = sTheta[ntA * 8 + tc * 2], tA1 = sTheta[ntA * 8 + tc * 2 + 1];
        const float tB0 = sTheta[ntB * 8 + tc * 2], tB1 = sTheta[ntB * 8 + tc * 2 + 1];
        float qa0 = __cosf(acc[ntA][0] + tA0);
        float qa1 = __cosf(acc[ntA][1] + tA1);
        float qa2 = __cosf(acc[ntA][2] + tA0);
        float qa3 = __cosf(acc[ntA][3] + tA1);
        float qb0 = __cosf(acc[ntB][0] + tB0);
        float qb1 = __cosf(acc[ntB][1] + tB1);
        float qb2 = __cosf(acc[ntB][2] + tB0);
        float qb3 = __cosf(acc[ntB][3] + tB1);
        split2(qa0, qa1, a2h[kt2][0], a2l[kt2][0]); // row gr,   k lo-half
        split2(qa2, qa3, a2h[kt2][1], a2l[kt2][1]); // row gr+8, k lo-half
        split2(qb0, qb1, a2h[kt2][2], a2l[kt2][2]); // row gr,   k hi-half
        split2(qb2, qb3, a2h[kt2][3], a2l[kt2][3]); // row gr+8, k hi-half
    }

    // ---------------- GEMM2: Y = q @ Wout^T (bf16x3, fp32 acc) ----------------
    float acc2[8][4];
#pragma unroll
    for (int nt = 0; nt < 8; nt++)
#pragma unroll
        for (int i = 0; i < 4; i++) acc2[nt][i] = 0.f;

#pragma unroll
    for (int kt2 = 0; kt2 < 4; kt2++) {
#pragma unroll
        for (int nt2 = 0; nt2 < 8; nt2++) {
            const uint4 q = sWout[(nt2 * 8 + gr) * RPQ + kt2 * 4 + tc];
            mma16816(acc2[nt2], a2h[kt2], q.x, q.y);
            mma16816(acc2[nt2], a2l[kt2], q.x, q.y);
            mma16816(acc2[nt2], a2h[kt2], q.z, q.w);
        }
    }

    // ---------------- Store: each 4-lane group writes contiguous 32B ----------------
    const size_t r0 = (size_t)(tok0 + gr);
#pragma unroll
    for (int nt2 = 0; nt2 < 8; nt2++) {
        float* po = out + r0 * 64 + nt2 * 8 + tc * 2;
        stcs2(po,          acc2[nt2][0], acc2[nt2][1]);
        stcs2(po + 8 * 64, acc2[nt2][2], acc2[nt2][3]);
    }
}

extern "C" void kernel_launch(void* const* d_in, const int* in_sizes, int n_in,
                              void* d_out, int out_size) {
    const float* x     = (const float*)d_in[0];
    const float* W_in  = (const float*)d_in[1];
    const float* theta = (const float*)d_in[2];
    const float* W_out = (const float*)d_in[3];
    float* out = (float*)d_out;

    quantum_fused_kernel<<<NCTAS, 256>>>(x, W_in, theta, W_out, out);
}

// round 4
// speedup vs baseline: 1.1548x; 1.1548x over previous
#include <cuda_runtime.h>
#include <cuda_bf16.h>
#include <stdint.h>

// Problem constants
#define NTOK   (32 * 8192)          // 262144 tokens
#define TILE_T 128                  // tokens per CTA (4 warps x 32)
#define NCTAS  (NTOK / TILE_T)      // 2048
#define RPQ    20                   // uint4 per smem W row: 20 % 8 == 4 -> LDS.128 conflict-free

// Split one float pair into bf16-hi and bf16-lo packed words (lo = residual).
__device__ __forceinline__ void split2(float x0, float x1, uint32_t& hi, uint32_t& lo) {
    __nv_bfloat16 h0 = __float2bfloat16(x0);
    __nv_bfloat16 h1 = __float2bfloat16(x1);
    __nv_bfloat16 l0 = __float2bfloat16(x0 - __bfloat162float(h0));
    __nv_bfloat16 l1 = __float2bfloat16(x1 - __bfloat162float(h1));
    hi = (uint32_t)__bfloat16_as_ushort(h0) | ((uint32_t)__bfloat16_as_ushort(h1) << 16);
    lo = (uint32_t)__bfloat16_as_ushort(l0) | ((uint32_t)__bfloat16_as_ushort(l1) << 16);
}

__device__ __forceinline__ void mma16816(float* c, const uint32_t* a, uint32_t b0, uint32_t b1) {
    asm volatile(
        "mma.sync.aligned.m16n8k16.row.col.f32.bf16.bf16.f32 "
        "{%0,%1,%2,%3}, {%4,%5,%6,%7}, {%8,%9}, {%0,%1,%2,%3};\n"
        : "+f"(c[0]), "+f"(c[1]), "+f"(c[2]), "+f"(c[3])
        : "r"(a[0]), "r"(a[1]), "r"(a[2]), "r"(a[3]), "r"(b0), "r"(b1));
}

__device__ __forceinline__ float2 ldcs2(const float* p) {
    float2 v;
    asm volatile("ld.global.cs.v2.f32 {%0,%1}, [%2];" : "=f"(v.x), "=f"(v.y) : "l"(p));
    return v;
}
__device__ __forceinline__ void stcs2(float* p, float a, float b) {
    asm volatile("st.global.cs.v2.f32 [%0], {%1,%2};" :: "l"(p), "f"(a), "f"(b));
}

__global__ void __launch_bounds__(128, 3)
quantum_fused_kernel(const float* __restrict__ x,
                     const float* __restrict__ Win,    // [64 wires][64 embed]
                     const float* __restrict__ theta,  // [64]
                     const float* __restrict__ Wout,   // [64 out][64 wires]
                     float* __restrict__ out)
{
    // Packed B-fragment quads: sW[row][kt*4+tc] = {hi(w), hi(w+4), lo(w), lo(w+4)},
    // w = kt*8+tc.  Pitch 20 uint4: phase slot = (4*gr + 4*kt + tc) mod 8 -> all
    // 8 lanes of each LDS.128 phase hit distinct 16B slots (zero bank conflicts).
    __shared__ uint4 sWin[64 * RPQ];
    __shared__ uint4 sWout[64 * RPQ];
    __shared__ float sTheta[64];

    const int tid = threadIdx.x;

    // One-time W split+pack: 64 rows x 16 packs per matrix, 128 threads.
    for (int idx = tid; idx < 64 * 16; idx += 128) {
        const int row = idx >> 4;
        const int p   = idx & 15;          // kt*4 + tc
        const int kt  = p >> 2, tc = p & 3;
        const int w   = kt * 8 + tc;       // float2-word index in row

        float2 a = ((const float2*)Win)[row * 32 + w];
        float2 b = ((const float2*)Win)[row * 32 + w + 4];
        uint4 q;
        split2(a.x, a.y, q.x, q.z);
        split2(b.x, b.y, q.y, q.w);
        sWin[row * RPQ + p] = q;

        a = ((const float2*)Wout)[row * 32 + w];
        b = ((const float2*)Wout)[row * 32 + w + 4];
        split2(a.x, a.y, q.x, q.z);
        split2(b.x, b.y, q.y, q.w);
        sWout[row * RPQ + p] = q;
    }
    if (tid < 64) sTheta[tid] = theta[tid];
    __syncthreads();

    const int lane = tid & 31;
    const int warp = tid >> 5;    // 0..3
    const int gr   = lane >> 2;   // group-of-4 id (row within 8)
    const int tc   = lane & 3;    // thread-in-group (col pair selector)

    const int tok0 = blockIdx.x * TILE_T + warp * 32;   // 32 tokens (2 m-tiles) per warp

    // ---------------- Front-batched x loads (32 x float2, streaming) ----------------
    float2 v[2][4][4];
#pragma unroll
    for (int mt = 0; mt < 2; mt++) {
        const float* px = x + (size_t)(tok0 + mt * 16 + gr) * 64 + tc * 2;
#pragma unroll
        for (int kt = 0; kt < 4; kt++) {
            v[mt][kt][0] = ldcs2(px + kt * 16);              // (gr,   kt*16+tc*2)
            v[mt][kt][1] = ldcs2(px + kt * 16 + 8 * 64);     // (gr+8, kt*16+tc*2)
            v[mt][kt][2] = ldcs2(px + kt * 16 + 8);          // (gr,   kt*16+tc*2+8)
            v[mt][kt][3] = ldcs2(px + kt * 16 + 8 * 64 + 8); // (gr+8, kt*16+tc*2+8)
        }
    }

    // ---------------- GEMM1: T = X @ Win^T (bf16x3, fp32 acc) ----------------
    float acc[2][8][4];
#pragma unroll
    for (int mt = 0; mt < 2; mt++)
#pragma unroll
        for (int nt = 0; nt < 8; nt++)
#pragma unroll
            for (int i = 0; i < 4; i++) acc[mt][nt][i] = 0.f;

#pragma unroll
    for (int kt = 0; kt < 4; kt++) {
        uint32_t ah[2][4], al[2][4];
#pragma unroll
        for (int mt = 0; mt < 2; mt++)
#pragma unroll
            for (int i = 0; i < 4; i++)
                split2(v[mt][kt][i].x, v[mt][kt][i].y, ah[mt][i], al[mt][i]);
#pragma unroll
        for (int nt = 0; nt < 8; nt++) {
            const uint4 q = sWin[(nt * 8 + gr) * RPQ + kt * 4 + tc];
#pragma unroll
            for (int mt = 0; mt < 2; mt++) {
                mma16816(acc[mt][nt], ah[mt], q.x, q.y);  // hi*hi
                mma16816(acc[mt][nt], al[mt], q.x, q.y);  // lo*hi
                mma16816(acc[mt][nt], ah[mt], q.z, q.w);  // hi*lo
            }
        }
    }

    // -------- q = cos(T + theta); repack C-frags directly into A-frags --------
    uint32_t a2h[2][4][4], a2l[2][4][4];
#pragma unroll
    for (int kt2 = 0; kt2 < 4; kt2++) {
        const int ntA = 2 * kt2, ntB = 2 * kt2 + 1;
        const float tA0 = sTheta[ntA * 8 + tc * 2], tA1 = sTheta[ntA * 8 + tc * 2 + 1];
        const float tB0 = sTheta[ntB * 8 + tc * 2], tB1 = sTheta[ntB * 8 + tc * 2 + 1];
#pragma unroll
        for (int mt = 0; mt < 2; mt++) {
            float qa0 = __cosf(acc[mt][ntA][0] + tA0);
            float qa1 = __cosf(acc[mt][ntA][1] + tA1);
            float qa2 = __cosf(acc[mt][ntA][2] + tA0);
            float qa3 = __cosf(acc[mt][ntA][3] + tA1);
            float qb0 = __cosf(acc[mt][ntB][0] + tB0);
            float qb1 = __cosf(acc[mt][ntB][1] + tB1);
            float qb2 = __cosf(acc[mt][ntB][2] + tB0);
            float qb3 = __cosf(acc[mt][ntB][3] + tB1);
            split2(qa0, qa1, a2h[mt][kt2][0], a2l[mt][kt2][0]); // row gr,   k lo-half
            split2(qa2, qa3, a2h[mt][kt2][1], a2l[mt][kt2][1]); // row gr+8, k lo-half
            split2(qb0, qb1, a2h[mt][kt2][2], a2l[mt][kt2][2]); // row gr,   k hi-half
            split2(qb2, qb3, a2h[mt][kt2][3], a2l[mt][kt2][3]); // row gr+8, k hi-half
        }
    }

    // ---------------- GEMM2: Y = q @ Wout^T (bf16x3, fp32 acc) ----------------
    float acc2[2][8][4];
#pragma unroll
    for (int mt = 0; mt < 2; mt++)
#pragma unroll
        for (int nt = 0; nt < 8; nt++)
#pragma unroll
            for (int i = 0; i < 4; i++) acc2[mt][nt][i] = 0.f;

#pragma unroll
    for (int kt2 = 0; kt2 < 4; kt2++) {
#pragma unroll
        for (int nt2 = 0; nt2 < 8; nt2++) {
            const uint4 q = sWout[(nt2 * 8 + gr) * RPQ + kt2 * 4 + tc];
#pragma unroll
            for (int mt = 0; mt < 2; mt++) {
                mma16816(acc2[mt][nt2], a2h[mt][kt2], q.x, q.y);
                mma16816(acc2[mt][nt2], a2l[mt][kt2], q.x, q.y);
                mma16816(acc2[mt][nt2], a2h[mt][kt2], q.z, q.w);
            }
        }
    }

    // ---------------- Store: each 4-lane group writes contiguous 32B ----------------
#pragma unroll
    for (int mt = 0; mt < 2; mt++) {
        const size_t r0 = (size_t)(tok0 + mt * 16 + gr);
#pragma unroll
        for (int nt2 = 0; nt2 < 8; nt2++) {
            float* po = out + r0 * 64 + nt2 * 8 + tc * 2;
            stcs2(po,          acc2[mt][nt2][0], acc2[mt][nt2][1]);
            stcs2(po + 8 * 64, acc2[mt][nt2][2], acc2[mt][nt2][3]);
        }
    }
}

extern "C" void kernel_launch(void* const* d_in, const int* in_sizes, int n_in,
                              void* d_out, int out_size) {
    const float* x     = (const float*)d_in[0];
    const float* W_in  = (const float*)d_in[1];
    const float* theta = (const float*)d_in[2];
    const float* W_out = (const float*)d_in[3];
    float* out = (float*)d_out;

    quantum_fused_kernel<<<NCTAS, 128>>>(x, W_in, theta, W_out, out);
}

// round 6
// speedup vs baseline: 1.2843x; 1.1122x over previous
#include <cuda_runtime.h>
#include <stdint.h>

// out = cos(X @ Win^T + theta) @ Wout^T
// X:[262144,64] fp32. Single-pass TF32 mma.sync m16n8k8 (rel_err ~4e-4 < 1e-3).
// K-slot permutation trick: mma k-slot (kt=2j+h, {tc,tc+4}) <-> phys col 16j+4tc+{2h,2h+1}
// -> coalesced LDG.128 for A, natural-order LDS.128 for Win, C-frag == next A-frag,
//    and (with Wout scrambled once at fill) STG.128 outputs.

#define NTOK   (32 * 8192)
#define TILE_T 128
#define NCTAS  (NTOK / TILE_T)    // 2048
#define PITCH4 20                 // uint4 per smem weight row (20%8==4 -> LDS.128 conflict-free)

__device__ __forceinline__ uint32_t tf32r(float x) {
    uint32_t u;
    asm("cvt.rna.tf32.f32 %0, %1;" : "=r"(u) : "f"(x));
    return u;
}

__device__ __forceinline__ void mma8(float* c, uint32_t a0, uint32_t a1, uint32_t a2, uint32_t a3,
                                     uint32_t b0, uint32_t b1) {
    asm volatile(
        "mma.sync.aligned.m16n8k8.row.col.f32.tf32.tf32.f32 "
        "{%0,%1,%2,%3}, {%4,%5,%6,%7}, {%8,%9}, {%0,%1,%2,%3};"
        : "+f"(c[0]), "+f"(c[1]), "+f"(c[2]), "+f"(c[3])
        : "r"(a0), "r"(a1), "r"(a2), "r"(a3), "r"(b0), "r"(b1));
}

__device__ __forceinline__ float4 ldcs4(const float* p) {
    float4 v;
    asm volatile("ld.global.cs.v4.f32 {%0,%1,%2,%3}, [%4];"
                 : "=f"(v.x), "=f"(v.y), "=f"(v.z), "=f"(v.w) : "l"(p));
    return v;
}
__device__ __forceinline__ void stcs4(float* p, float a, float b, float c, float d) {
    asm volatile("st.global.cs.v4.f32 [%0], {%1,%2,%3,%4};"
                 :: "l"(p), "f"(a), "f"(b), "f"(c), "f"(d));
}

// Wout slot-row s holds global row g(s): within each 16-group,
// u -> goff: u=2t->4t, 2t+1->4t+1, 8+2t->4t+2, 8+2t+1->4t+3.
// Inverse (global row offset p -> slot offset u):
__device__ __forceinline__ int ginv_off(int p) {
    return ((p & 2) >> 1) * 8 + ((p >> 2) & 3) * 2 + (p & 1);
}
// Wout k-columns: slot col c' = 16j + 4tc + 2hb + lb stores global col 16j + 8hb + 2tc + lb.
// Forward (global col w -> slot col):
__device__ __forceinline__ int hcol(int w) {
    return (w & ~15) | (((w & 7) >> 1) << 2) | (((w >> 3) & 1) << 1) | (w & 1);
}

__global__ void __launch_bounds__(128, 3)
quantum_tf32_kernel(const float* __restrict__ x,
                    const float* __restrict__ Win,    // [64][64]
                    const float* __restrict__ theta,  // [64]
                    const float* __restrict__ Wout,   // [64][64]
                    float* __restrict__ out)
{
    __shared__ uint32_t sWin[64 * PITCH4 * 4];   // tf32 bits, natural [n][k], pitch 80 words
    __shared__ uint32_t sWout[64 * PITCH4 * 4];  // tf32 bits, row+col scrambled
    __shared__ float    sTh[64];

    const int tid = threadIdx.x;

    // ---- Fill Win: natural layout, vector stores ----
    for (int idx = tid; idx < 1024; idx += 128) {
        const int r = idx >> 4, q = idx & 15;
        float4 w = ldcs4(Win + r * 64 + q * 4);
        uint4 u = make_uint4(tf32r(w.x), tf32r(w.y), tf32r(w.z), tf32r(w.w));
        *(uint4*)&sWin[(r * PITCH4 + q) * 4] = u;
    }
    // ---- Fill Wout: coalesced gmem read, scattered smem write (one-time) ----
    for (int idx = tid; idx < 1024; idx += 128) {
        const int r = idx >> 4, q = idx & 15;
        float4 w = ldcs4(Wout + r * 64 + q * 4);
        const int s = (r & ~15) | ginv_off(r & 15);
        uint32_t* row = &sWout[s * PITCH4 * 4];
        row[hcol(q * 4 + 0)] = tf32r(w.x);
        row[hcol(q * 4 + 1)] = tf32r(w.y);
        row[hcol(q * 4 + 2)] = tf32r(w.z);
        row[hcol(q * 4 + 3)] = tf32r(w.w);
    }
    if (tid < 64) sTh[tid] = theta[tid];
    __syncthreads();

    const int lane = tid & 31;
    const int warp = tid >> 5;    // 0..3
    const int gr   = lane >> 2;
    const int tc   = lane & 3;

    const int tok0 = blockIdx.x * TILE_T + warp * 32;   // 32 tokens (2 m-tiles) per warp

    // ---- A: coalesced LDG.128, cvt to tf32 in registers ----
    // xa[mt][rowhalf][j] covers phys cols 16j+4tc..+3 of rows (tok0+mt*16+gr [+8])
    uint32_t xa[2][2][4][4];
#pragma unroll
    for (int mt = 0; mt < 2; mt++) {
        const size_t r0 = (size_t)(tok0 + mt * 16 + gr);
#pragma unroll
        for (int j = 0; j < 4; j++) {
            float4 v0 = ldcs4(x + r0 * 64 + j * 16 + tc * 4);
            float4 v1 = ldcs4(x + (r0 + 8) * 64 + j * 16 + tc * 4);
            xa[mt][0][j][0] = tf32r(v0.x); xa[mt][0][j][1] = tf32r(v0.y);
            xa[mt][0][j][2] = tf32r(v0.z); xa[mt][0][j][3] = tf32r(v0.w);
            xa[mt][1][j][0] = tf32r(v1.x); xa[mt][1][j][1] = tf32r(v1.y);
            xa[mt][1][j][2] = tf32r(v1.z); xa[mt][1][j][3] = tf32r(v1.w);
        }
    }

    float acc2[2][8][4];
#pragma unroll
    for (int mt = 0; mt < 2; mt++)
#pragma unroll
        for (int nt = 0; nt < 8; nt++)
#pragma unroll
            for (int i = 0; i < 4; i++) acc2[mt][nt][i] = 0.f;

    // ---- Chunked pipeline: per pair of wire-chunks (j2), GEMM1 -> cos -> GEMM2 ----
#pragma unroll
    for (int j2 = 0; j2 < 4; j2++) {
        float t[2][2][4];   // [e: chunk in pair][mt][4]
#pragma unroll
        for (int e = 0; e < 2; e++)
#pragma unroll
            for (int mt = 0; mt < 2; mt++)
#pragma unroll
                for (int i = 0; i < 4; i++) t[e][mt][i] = 0.f;

        // GEMM1: t[e][mt] = X @ Win^T for wires [8*(2*j2+e), +8)
#pragma unroll
        for (int j = 0; j < 4; j++) {
#pragma unroll
            for (int e = 0; e < 2; e++) {
                const int nt = 2 * j2 + e;
                const uint4 b = *(const uint4*)&sWin[((8 * nt + gr) * PITCH4 + j * 4 + tc) * 4];
#pragma unroll
                for (int mt = 0; mt < 2; mt++) {
                    mma8(t[e][mt], xa[mt][0][j][0], xa[mt][1][j][0],
                                   xa[mt][0][j][1], xa[mt][1][j][1], b.x, b.y);
                    mma8(t[e][mt], xa[mt][0][j][2], xa[mt][1][j][2],
                                   xa[mt][0][j][3], xa[mt][1][j][3], b.z, b.w);
                }
            }
        }

        // q = cos(t + theta); C-frag (c0,c2,c1,c3) -> A-frag (a0,a1,a2,a3)
        uint32_t a2f[2][2][4];
#pragma unroll
        for (int e = 0; e < 2; e++) {
            const int nt = 2 * j2 + e;
            const float2 tb = *(const float2*)&sTh[8 * nt + 2 * tc];
#pragma unroll
            for (int mt = 0; mt < 2; mt++) {
                a2f[e][mt][0] = tf32r(__cosf(t[e][mt][0] + tb.x));
                a2f[e][mt][1] = tf32r(__cosf(t[e][mt][2] + tb.x));
                a2f[e][mt][2] = tf32r(__cosf(t[e][mt][1] + tb.y));
                a2f[e][mt][3] = tf32r(__cosf(t[e][mt][3] + tb.y));
            }
        }

        // GEMM2 partial: acc2 += q(wires of this pair) @ Wout^T
#pragma unroll
        for (int nt2 = 0; nt2 < 8; nt2++) {
            const uint4 b2 = *(const uint4*)&sWout[((8 * nt2 + gr) * PITCH4 + j2 * 4 + tc) * 4];
#pragma unroll
            for (int mt = 0; mt < 2; mt++) {
                mma8(acc2[mt][nt2], a2f[0][mt][0], a2f[0][mt][1],
                                    a2f[0][mt][2], a2f[0][mt][3], b2.x, b2.y);
                mma8(acc2[mt][nt2], a2f[1][mt][0], a2f[1][mt][1],
                                    a2f[1][mt][2], a2f[1][mt][3], b2.z, b2.w);
            }
        }
    }

    // ---- Stores: Wout row-scramble makes per-thread cols contiguous -> STG.128 ----
#pragma unroll
    for (int mt = 0; mt < 2; mt++) {
        const size_t r0 = (size_t)(tok0 + mt * 16 + gr);
#pragma unroll
        for (int j2o = 0; j2o < 4; j2o++) {
            const int nA = 2 * j2o, nB = nA + 1;
            const int col = j2o * 16 + tc * 4;
            stcs4(out + r0 * 64 + col,
                  acc2[mt][nA][0], acc2[mt][nA][1], acc2[mt][nB][0], acc2[mt][nB][1]);
            stcs4(out + (r0 + 8) * 64 + col,
                  acc2[mt][nA][2], acc2[mt][nA][3], acc2[mt][nB][2], acc2[mt][nB][3]);
        }
    }
}

extern "C" void kernel_launch(void* const* d_in, const int* in_sizes, int n_in,
                              void* d_out, int out_size) {
    const float* x     = (const float*)d_in[0];
    const float* W_in  = (const float*)d_in[1];
    const float* theta = (const float*)d_in[2];
    const float* W_out = (const float*)d_in[3];
    float* out = (float*)d_out;

    quantum_tf32_kernel<<<NCTAS, 128>>>(x, W_in, theta, W_out, out);
}

// round 7
// speedup vs baseline: 1.6077x; 1.2518x over previous
#include <cuda_runtime.h>
#include <stdint.h>

// out = cos(X @ Win^T + theta) @ Wout^T      X:[262144,64] fp32
// Single-pass TF32 mma.sync m16n8k8 (rel_err ~4e-4 < 1e-3).
// K-slot permutation trick (validated R6): coalesced LDG.128 for A, natural-order
// LDS.128 for Win, C-frag == next A-frag, scrambled Wout -> STG.128 outputs.
// R7: two-phase structure (full GEMM1 -> cos -> GEMM2 per output pair) to cut
// register pressure; 256-thread CTAs, __launch_bounds__(256,2).

#define NTOK   (32 * 8192)
#define TILE_T 256                 // tokens per CTA (8 warps x 32)
#define NCTAS  (NTOK / TILE_T)     // 1024
#define PITCH4 20                  // uint4 per smem weight row (20%8==4 -> conflict-free)

__device__ __forceinline__ uint32_t tf32r(float x) {
    uint32_t u;
    asm("cvt.rna.tf32.f32 %0, %1;" : "=r"(u) : "f"(x));
    return u;
}

__device__ __forceinline__ void mma8(float* c, uint32_t a0, uint32_t a1, uint32_t a2, uint32_t a3,
                                     uint32_t b0, uint32_t b1) {
    asm volatile(
        "mma.sync.aligned.m16n8k8.row.col.f32.tf32.tf32.f32 "
        "{%0,%1,%2,%3}, {%4,%5,%6,%7}, {%8,%9}, {%0,%1,%2,%3};"
        : "+f"(c[0]), "+f"(c[1]), "+f"(c[2]), "+f"(c[3])
        : "r"(a0), "r"(a1), "r"(a2), "r"(a3), "r"(b0), "r"(b1));
}

__device__ __forceinline__ float4 ldcs4(const float* p) {
    float4 v;
    asm volatile("ld.global.cs.v4.f32 {%0,%1,%2,%3}, [%4];"
                 : "=f"(v.x), "=f"(v.y), "=f"(v.z), "=f"(v.w) : "l"(p));
    return v;
}
__device__ __forceinline__ void stcs4(float* p, float a, float b, float c, float d) {
    asm volatile("st.global.cs.v4.f32 [%0], {%1,%2,%3,%4};"
                 :: "l"(p), "f"(a), "f"(b), "f"(c), "f"(d));
}

// Wout row scramble (global row offset p -> slot offset u) and col scramble.
__device__ __forceinline__ int ginv_off(int p) {
    return ((p & 2) >> 1) * 8 + ((p >> 2) & 3) * 2 + (p & 1);
}
__device__ __forceinline__ int hcol(int w) {
    return (w & ~15) | (((w & 7) >> 1) << 2) | (((w >> 3) & 1) << 1) | (w & 1);
}

__global__ void __launch_bounds__(256, 2)
quantum_tf32_kernel(const float* __restrict__ x,
                    const float* __restrict__ Win,    // [64][64]
                    const float* __restrict__ theta,  // [64]
                    const float* __restrict__ Wout,   // [64][64]
                    float* __restrict__ out)
{
    __shared__ uint32_t sWin[64 * PITCH4 * 4];   // tf32 bits, natural [n][k]
    __shared__ uint32_t sWout[64 * PITCH4 * 4];  // tf32 bits, row+col scrambled
    __shared__ float    sTh[64];

    const int tid = threadIdx.x;

    // ---- Fill Win (natural) and Wout (scrambled), one-time ----
    for (int idx = tid; idx < 1024; idx += 256) {
        const int r = idx >> 4, q = idx & 15;
        float4 w = ldcs4(Win + r * 64 + q * 4);
        *(uint4*)&sWin[(r * PITCH4 + q) * 4] =
            make_uint4(tf32r(w.x), tf32r(w.y), tf32r(w.z), tf32r(w.w));
    }
    for (int idx = tid; idx < 1024; idx += 256) {
        const int r = idx >> 4, q = idx & 15;
        float4 w = ldcs4(Wout + r * 64 + q * 4);
        const int s = (r & ~15) | ginv_off(r & 15);
        uint32_t* row = &sWout[s * PITCH4 * 4];
        row[hcol(q * 4 + 0)] = tf32r(w.x);
        row[hcol(q * 4 + 1)] = tf32r(w.y);
        row[hcol(q * 4 + 2)] = tf32r(w.z);
        row[hcol(q * 4 + 3)] = tf32r(w.w);
    }
    if (tid < 64) sTh[tid] = theta[tid];
    __syncthreads();

    const int lane = tid & 31;
    const int warp = tid >> 5;    // 0..7
    const int gr   = lane >> 2;
    const int tc   = lane & 3;

    const int tok0 = blockIdx.x * TILE_T + warp * 32;   // 32 tokens (2 m-tiles) per warp

    // ---- Phase 0: coalesced LDG.128 of A, cvt to tf32 ----
    uint32_t xa[2][2][4][4];
#pragma unroll
    for (int mt = 0; mt < 2; mt++) {
        const size_t r0 = (size_t)(tok0 + mt * 16 + gr);
#pragma unroll
        for (int j = 0; j < 4; j++) {
            float4 v0 = ldcs4(x + r0 * 64 + j * 16 + tc * 4);
            float4 v1 = ldcs4(x + (r0 + 8) * 64 + j * 16 + tc * 4);
            xa[mt][0][j][0] = tf32r(v0.x); xa[mt][0][j][1] = tf32r(v0.y);
            xa[mt][0][j][2] = tf32r(v0.z); xa[mt][0][j][3] = tf32r(v0.w);
            xa[mt][1][j][0] = tf32r(v1.x); xa[mt][1][j][1] = tf32r(v1.y);
            xa[mt][1][j][2] = tf32r(v1.z); xa[mt][1][j][3] = tf32r(v1.w);
        }
    }

    // ---- Phase 1: full GEMM1, 16 independent accumulator chains ----
    float t[2][8][4];
#pragma unroll
    for (int mt = 0; mt < 2; mt++)
#pragma unroll
        for (int nt = 0; nt < 8; nt++)
#pragma unroll
            for (int i = 0; i < 4; i++) t[mt][nt][i] = 0.f;

#pragma unroll
    for (int j = 0; j < 4; j++) {
#pragma unroll
        for (int nt = 0; nt < 8; nt++) {
            const uint4 b = *(const uint4*)&sWin[((8 * nt + gr) * PITCH4 + j * 4 + tc) * 4];
#pragma unroll
            for (int mt = 0; mt < 2; mt++) {
                mma8(t[mt][nt], xa[mt][0][j][0], xa[mt][1][j][0],
                                xa[mt][0][j][1], xa[mt][1][j][1], b.x, b.y);
                mma8(t[mt][nt], xa[mt][0][j][2], xa[mt][1][j][2],
                                xa[mt][0][j][3], xa[mt][1][j][3], b.z, b.w);
            }
        }
    }
    // xa dead here.

    // ---- Phase 1.5: q = cos(t + theta), C-frag(c0,c2,c1,c3) -> A-frag, tf32 ----
    uint32_t a2f[2][8][4];
#pragma unroll
    for (int nt = 0; nt < 8; nt++) {
        const float2 tb = *(const float2*)&sTh[8 * nt + 2 * tc];
#pragma unroll
        for (int mt = 0; mt < 2; mt++) {
            a2f[mt][nt][0] = tf32r(__cosf(t[mt][nt][0] + tb.x));
            a2f[mt][nt][1] = tf32r(__cosf(t[mt][nt][2] + tb.x));
            a2f[mt][nt][2] = tf32r(__cosf(t[mt][nt][1] + tb.y));
            a2f[mt][nt][3] = tf32r(__cosf(t[mt][nt][3] + tb.y));
        }
    }
    // t dead here.

    // ---- Phase 2: GEMM2 per output-column pair, store immediately ----
#pragma unroll
    for (int np = 0; np < 4; np++) {          // output nt2 pair {2np, 2np+1}
        float acc[2][2][4];
#pragma unroll
        for (int mt = 0; mt < 2; mt++)
#pragma unroll
            for (int e = 0; e < 2; e++)
#pragma unroll
                for (int i = 0; i < 4; i++) acc[mt][e][i] = 0.f;

#pragma unroll
        for (int j2 = 0; j2 < 4; j2++) {      // K (wire) chunks
#pragma unroll
            for (int e = 0; e < 2; e++) {
                const int nt2 = 2 * np + e;
                const uint4 b2 = *(const uint4*)&sWout[((8 * nt2 + gr) * PITCH4 + j2 * 4 + tc) * 4];
#pragma unroll
                for (int mt = 0; mt < 2; mt++) {
                    mma8(acc[mt][e], a2f[mt][2 * j2][0], a2f[mt][2 * j2][1],
                                     a2f[mt][2 * j2][2], a2f[mt][2 * j2][3], b2.x, b2.y);
                    mma8(acc[mt][e], a2f[mt][2 * j2 + 1][0], a2f[mt][2 * j2 + 1][1],
                                     a2f[mt][2 * j2 + 1][2], a2f[mt][2 * j2 + 1][3], b2.z, b2.w);
                }
            }
        }

        const int col = np * 16 + tc * 4;
#pragma unroll
        for (int mt = 0; mt < 2; mt++) {
            const size_t r0 = (size_t)(tok0 + mt * 16 + gr);
            stcs4(out + r0 * 64 + col,
                  acc[mt][0][0], acc[mt][0][1], acc[mt][1][0], acc[mt][1][1]);
            stcs4(out + (r0 + 8) * 64 + col,
                  acc[mt][0][2], acc[mt][0][3], acc[mt][1][2], acc[mt][1][3]);
        }
    }
}

extern "C" void kernel_launch(void* const* d_in, const int* in_sizes, int n_in,
                              void* d_out, int out_size) {
    const float* x     = (const float*)d_in[0];
    const float* W_in  = (const float*)d_in[1];
    const float* theta = (const float*)d_in[2];
    const float* W_out = (const float*)d_in[3];
    float* out = (float*)d_out;

    quantum_tf32_kernel<<<NCTAS, 256>>>(x, W_in, theta, W_out, out);
}